// round 1
// baseline (speedup 1.0000x reference)
#include <cuda_runtime.h>
#include <math.h>

// Problem constants (fixed by setup_inputs)
#define NN   10240
#define DD   256
#define TOPK 31          // k+1 with k=30
#define BM   64
#define BN   64
#define BSTR (DD + 4)    // padded row stride in smem (floats)

// Scratch: normalized embeddings (10240*256 fp32 = 10.5 MB)
__device__ float g_emb[(size_t)NN * DD];

// ---------------------------------------------------------------------------
// Kernel 1: h = relu(x*w1)*w2 ; emb = h / max(||h||_2, 1e-12). One block/row.
// ---------------------------------------------------------------------------
__global__ void emb_kernel(const float* __restrict__ f,
                           const float* __restrict__ w1,
                           const float* __restrict__ w2) {
    int row = blockIdx.x;
    int d   = threadIdx.x;            // 256 threads == DD
    float x = f[(size_t)row * DD + d];
    float h = fmaxf(x * w1[d], 0.0f) * w2[d];
    float s = h * h;
    __shared__ float red[8];
    #pragma unroll
    for (int o = 16; o > 0; o >>= 1) s += __shfl_xor_sync(0xffffffffu, s, o);
    if ((d & 31) == 0) red[d >> 5] = s;
    __syncthreads();
    if (d < 32) {
        float t = (d < 8) ? red[d] : 0.0f;
        #pragma unroll
        for (int o = 4; o > 0; o >>= 1) t += __shfl_xor_sync(0xffffffffu, t, o);
        if (d == 0) red[0] = t;
    }
    __syncthreads();
    float norm = fmaxf(sqrtf(red[0]), 1e-12f);
    g_emb[(size_t)row * DD + d] = h / norm;
}

// ---------------------------------------------------------------------------
// Kernel 2: fused sim-GEMM (fp32) + streaming per-row top-31 + scatter.
// Each block owns BM=64 rows, loops over all 160 column tiles of BN=64.
// ---------------------------------------------------------------------------
__global__ __launch_bounds__(256)
void simtopk_kernel(float* __restrict__ out) {
    extern __shared__ char smem_raw[];
    float* As    = (float*)smem_raw;                 // BM * BSTR
    float* Bs    = As + BM * BSTR;                   // BN * BSTR
    float* Cs    = Bs + BN * BSTR;                   // BM * (BN+1)
    float* tv    = Cs + BM * (BN + 1);               // BM * TOPK values
    int*   ti    = (int*)(tv + BM * TOPK);           // BM * TOPK indices
    float* tmin  = (float*)(ti + BM * TOPK);         // BM current list-min
    int*   tslot = (int*)(tmin + BM);                // BM slot of list-min

    const int tid  = threadIdx.x;
    const int rb   = blockIdx.x * BM;
    const int tc   = tid & 15, tr = tid >> 4;
    const int warp = tid >> 5, lane = tid & 31;

    // Load A tile (persistent for the whole block)
    for (int i = tid; i < BM * (DD / 4); i += 256) {
        int r = i >> 6, c4 = i & 63;
        float4 v = *(const float4*)&g_emb[(size_t)(rb + r) * DD + c4 * 4];
        *(float4*)&As[r * BSTR + c4 * 4] = v;
    }
    // Init top-k lists
    for (int i = tid; i < BM * TOPK; i += 256) { tv[i] = -1e30f; ti[i] = 0; }
    if (tid < BM) { tmin[tid] = -1e30f; tslot[tid] = 0; }

    for (int ct = 0; ct < NN / BN; ++ct) {
        // Load B tile
        for (int i = tid; i < BN * (DD / 4); i += 256) {
            int r = i >> 6, c4 = i & 63;
            float4 v = *(const float4*)&g_emb[(size_t)(ct * BN + r) * DD + c4 * 4];
            *(float4*)&Bs[r * BSTR + c4 * 4] = v;
        }
        __syncthreads();

        // 64x64 fp32 tile: each thread computes 4x4 outputs
        float acc[4][4];
        #pragma unroll
        for (int i = 0; i < 4; ++i)
            #pragma unroll
            for (int j = 0; j < 4; ++j) acc[i][j] = 0.0f;

        const float* Ab = &As[(tr * 4) * BSTR];
        const float* Bb = &Bs[(tc * 4) * BSTR];
        #pragma unroll 4
        for (int d4 = 0; d4 < DD / 4; ++d4) {
            float4 a[4], b[4];
            #pragma unroll
            for (int i = 0; i < 4; ++i) a[i] = *(const float4*)&Ab[i * BSTR + d4 * 4];
            #pragma unroll
            for (int j = 0; j < 4; ++j) b[j] = *(const float4*)&Bb[j * BSTR + d4 * 4];
            #pragma unroll
            for (int i = 0; i < 4; ++i)
                #pragma unroll
                for (int j = 0; j < 4; ++j)
                    acc[i][j] += a[i].x * b[j].x + a[i].y * b[j].y
                               + a[i].z * b[j].z + a[i].w * b[j].w;
        }

        // Stage tile to smem for the top-k scan
        #pragma unroll
        for (int i = 0; i < 4; ++i)
            #pragma unroll
            for (int j = 0; j < 4; ++j)
                Cs[(tr * 4 + i) * (BN + 1) + tc * 4 + j] = acc[i][j];
        __syncthreads();

        // Streaming top-31 update: each warp owns 8 rows
        for (int rr = 0; rr < 8; ++rr) {
            int r = warp * 8 + rr;
            #pragma unroll
            for (int h = 0; h < 2; ++h) {
                int c = lane + h * 32;
                float v = Cs[r * (BN + 1) + c];
                int gi = ct * BN + c;
                float m = tmin[r];   // stale read is safe: min only grows
                unsigned ball = __ballot_sync(0xffffffffu, v > m);
                while (ball) {
                    int src = __ffs(ball) - 1;
                    ball &= ball - 1;
                    float vv = __shfl_sync(0xffffffffu, v, src);
                    int   ii = __shfl_sync(0xffffffffu, gi, src);
                    if (lane == 0 && vv > tmin[r]) {   // exact recheck by owner
                        int slot = tslot[r];
                        tv[r * TOPK + slot] = vv;
                        ti[r * TOPK + slot] = ii;
                        float mn = tv[r * TOPK]; int ms = 0;
                        #pragma unroll
                        for (int s2 = 1; s2 < TOPK; ++s2) {
                            float xv = tv[r * TOPK + s2];
                            if (xv < mn) { mn = xv; ms = s2; }
                        }
                        tmin[r] = mn; tslot[r] = ms;
                    }
                }
            }
        }
        __syncthreads();   // scan done before next B load / C overwrite
    }

    // Scatter: out already zeroed; write relu(top values)
    for (int rr = 0; rr < 8; ++rr) {
        int r = warp * 8 + rr;
        if (lane < TOPK) {
            float v  = tv[r * TOPK + lane];
            int   id = ti[r * TOPK + lane];
            out[(size_t)(rb + r) * NN + id] = fmaxf(v, 0.0f);
        }
    }
}

// ---------------------------------------------------------------------------
extern "C" void kernel_launch(void* const* d_in, const int* in_sizes, int n_in,
                              void* d_out, int out_size) {
    const float* f  = (const float*)d_in[0];
    const float* w1 = (const float*)d_in[1];
    const float* w2 = (const float*)d_in[2];
    float* out = (float*)d_out;

    // Zero the 419 MB output (memset node in the graph)
    cudaMemsetAsync(out, 0, (size_t)NN * NN * sizeof(float), 0);

    emb_kernel<<<NN, DD>>>(f, w1, w2);

    size_t smem = (size_t)(BM * BSTR + BN * BSTR + BM * (BN + 1) + BM * TOPK) * sizeof(float)
                + (size_t)BM * TOPK * sizeof(int)
                + (size_t)BM * (sizeof(float) + sizeof(int));
    cudaFuncSetAttribute(simtopk_kernel,
                         cudaFuncAttributeMaxDynamicSharedMemorySize, (int)smem);
    simtopk_kernel<<<NN / BM, 256, smem>>>(out);
}

// round 12
// speedup vs baseline: 3.0706x; 3.0706x over previous
#include <cuda_runtime.h>
#include <cuda_fp16.h>
#include <math.h>
#include <stdint.h>

// ---------------------------------------------------------------------------
// Problem constants
// ---------------------------------------------------------------------------
#define NN    10240
#define DD    256
#define TOPK  31         // final k+1
#define KA    32         // per-chunk candidate list size (register-resident)
#define NCC   4          // column chunks per row
#define CTPB  20         // col tiles (128) per chunk: 4*20*128 = 10240
#define RT    80         // row tiles (NN/128)
#define NCH   8          // K chunks of 32 per tile
#define NCAND 64         // rescored candidates per row

// Scratch (device globals — no allocation allowed)
__device__ float  g_emb[(size_t)NN * DD];
__device__ __half g_hi[(size_t)NN * DD];
__device__ __half g_lo[(size_t)NN * DD];
__device__ float g_pv[(size_t)NN * NCC * KA];
__device__ int   g_pi[(size_t)NN * NCC * KA];

// ---------------------------------------------------------------------------
// Smem layout (bytes) for GEMM kernel.
// A stride 528B; B stride 80B (both conflict-free for ldmatrix).
// ---------------------------------------------------------------------------
#define SM_AHI 0u
#define SM_ALO 67584u        // 128*528
#define SM_BB  135168u       // two bufs of 20480 (hi 10240 + lo 10240)
#define BUFSZ  20480u
#define SM_CS  135168u       // C staging overlays B-buffer region
#define CS_STR 68
#define SM_TMN 176128u       // 128 fp32 (stale filter mins)
#define SM_END 176640u

// ---------------------------------------------------------------------------
// PTX helpers (baseline sm_80-era features; compile for plain sm_103)
// ---------------------------------------------------------------------------
__device__ __forceinline__ uint32_t s2u(const void* p) {
    uint32_t a;
    asm("{ .reg .u64 t; cvta.to.shared.u64 t, %1; cvt.u32.u64 %0, t; }"
        : "=r"(a) : "l"(p));
    return a;
}
__device__ __forceinline__ void cpa16(uint32_t s, const void* g) {
    asm volatile(
        "{ .reg .u64 gg; cvta.to.global.u64 gg, %1; "
        "cp.async.cg.shared.global [%0], [gg], 16; }"
        :: "r"(s), "l"(g) : "memory");
}
#define CPA_COMMIT() asm volatile("cp.async.commit_group;" ::: "memory")
#define CPA_WAIT0()  asm volatile("cp.async.wait_group 0;" ::: "memory")

__device__ __forceinline__ void ldm4(uint32_t* r, uint32_t a) {
    asm volatile("ldmatrix.sync.aligned.m8n8.x4.shared.b16 {%0,%1,%2,%3}, [%4];"
                 : "=r"(r[0]), "=r"(r[1]), "=r"(r[2]), "=r"(r[3]) : "r"(a));
}
__device__ __forceinline__ void mma_f16(float* d, const uint32_t* a,
                                        uint32_t b0, uint32_t b1) {
    asm volatile(
        "mma.sync.aligned.m16n8k16.row.col.f32.f16.f16.f32 "
        "{%0,%1,%2,%3}, {%4,%5,%6,%7}, {%8,%9}, {%0,%1,%2,%3};"
        : "+f"(d[0]), "+f"(d[1]), "+f"(d[2]), "+f"(d[3])
        : "r"(a[0]), "r"(a[1]), "r"(a[2]), "r"(a[3]), "r"(b0), "r"(b1));
}

// ---------------------------------------------------------------------------
// Kernel 1: h = relu(x*w1)*w2; emb = h/max(||h||,1e-12).
// Stores fp32 emb (for rescoring) and fp16 hi/lo split (for MMA).
// ---------------------------------------------------------------------------
__global__ void emb_kernel(const float* __restrict__ f,
                           const float* __restrict__ w1,
                           const float* __restrict__ w2) {
    int row = blockIdx.x;
    int d   = threadIdx.x;            // 256 == DD
    float x = f[(size_t)row * DD + d];
    float h = fmaxf(x * w1[d], 0.0f) * w2[d];
    float s = h * h;
    __shared__ float red[8];
    #pragma unroll
    for (int o = 16; o > 0; o >>= 1) s += __shfl_xor_sync(0xffffffffu, s, o);
    if ((d & 31) == 0) red[d >> 5] = s;
    __syncthreads();
    if (d < 32) {
        float t = (d < 8) ? red[d] : 0.0f;
        #pragma unroll
        for (int o = 4; o > 0; o >>= 1) t += __shfl_xor_sync(0xffffffffu, t, o);
        if (d == 0) red[0] = t;
    }
    __syncthreads();
    float norm = fmaxf(sqrtf(red[0]), 1e-12f);
    float e = h / norm;
    size_t idx = (size_t)row * DD + d;
    g_emb[idx] = e;
    __half hb = __float2half_rn(e);
    g_hi[idx] = hb;
    g_lo[idx] = __float2half_rn(e - __half2float(hb));
}

// ---------------------------------------------------------------------------
// B chunk loader: rows ct*128..+127, K cols [c*32, c*32+32), hi+lo
// ---------------------------------------------------------------------------
__device__ __forceinline__ void load_B_chunk(uint32_t sb, int ct, int c,
                                             int buf, int tid) {
    uint32_t bbase = sb + SM_BB + (uint32_t)buf * BUFSZ;
    #pragma unroll
    for (int q = 0; q < 4; ++q) {
        int i = tid + q * 256;            // 1024 x 16B transfers
        int arr = i >> 9, rem = i & 511;
        int n = rem >> 2, seg = rem & 3;
        const __half* src = arr ? g_lo : g_hi;
        const void* g = &src[(size_t)(ct * 128 + n) * DD + c * 32 + seg * 8];
        uint32_t s = bbase + (uint32_t)arr * 10240u
                   + (uint32_t)n * 80u + (uint32_t)seg * 16u;
        cpa16(s, g);
    }
}

// ---------------------------------------------------------------------------
// Kernel 2: fp16-split (3-term) MMA GEMM + register-resident per-row top-32
// candidate lists. Block = (rt, cc): 128 rows x 2560 cols (20 tiles of 128).
// ---------------------------------------------------------------------------
__global__ __launch_bounds__(256, 1)
void gemm_cand_kernel(int _unused) {
    extern __shared__ __align__(16) char sm[];
    uint32_t sb = s2u(sm);

    const int tid   = threadIdx.x;
    const int wid   = tid >> 5, lane = tid & 31;
    const int warpm = wid >> 1, warpn = wid & 1;
    const int rt    = blockIdx.x >> 2;
    const int cc    = blockIdx.x & 3;
    const int rb    = rt * 128;

    // ---- persistent A tile (hi+lo), cp.async -----------------------------
    #pragma unroll
    for (int q = 0; q < 32; ++q) {
        int i = tid + q * 256;            // 8192 x 16B
        int arr = i >> 12, rem = i & 4095;
        int m = rem >> 5, seg = rem & 31;
        const __half* src = arr ? g_lo : g_hi;
        const void* g = &src[(size_t)(rb + m) * DD + seg * 8];
        uint32_t s = sb + (arr ? SM_ALO : SM_AHI)
                   + (uint32_t)m * 528u + (uint32_t)seg * 16u;
        cpa16(s, g);
    }
    CPA_COMMIT();

    float* tmn = (float*)(sm + SM_TMN);
    float* Cs  = (float*)(sm + SM_CS);
    if (tid < 128) tmn[tid] = -1e30f;

    // register-resident candidate lists: warp owns rows wid*16..+15,
    // one list slot per lane per row
    float rtv[16]; int rti[16];
    #pragma unroll
    for (int rr = 0; rr < 16; ++rr) { rtv[rr] = -1e30f; rti[rr] = 0; }

    CPA_WAIT0();
    __syncthreads();

    for (int t = 0; t < CTPB; ++t) {
        const int ct = cc * CTPB + t;

        float acc[2][8][4];
        #pragma unroll
        for (int i = 0; i < 2; ++i)
            #pragma unroll
            for (int j = 0; j < 8; ++j)
                #pragma unroll
                for (int q = 0; q < 4; ++q) acc[i][j][q] = 0.0f;

        load_B_chunk(sb, ct, 0, 0, tid);
        CPA_COMMIT(); CPA_WAIT0();
        __syncthreads();

        for (int c = 0; c < NCH; ++c) {
            if (c + 1 < NCH) {
                load_B_chunk(sb, ct, c + 1, (c + 1) & 1, tid);
                CPA_COMMIT();
            }
            uint32_t bbase = sb + SM_BB + (uint32_t)(c & 1) * BUFSZ;

            #pragma unroll
            for (int s = 0; s < 2; ++s) {        // two k16 steps per chunk
                uint32_t a[2][2][4];
                #pragma unroll
                for (int i = 0; i < 2; ++i)
                    #pragma unroll
                    for (int arr = 0; arr < 2; ++arr) {
                        uint32_t addr = sb + (arr ? SM_ALO : SM_AHI)
                            + (uint32_t)(warpm * 32 + i * 16 + (lane & 15)) * 528u
                            + (uint32_t)(c * 64 + s * 32 + (lane >> 4) * 16);
                        ldm4(a[i][arr], addr);
                    }
                uint32_t b[4][2][4];
                #pragma unroll
                for (int j2 = 0; j2 < 4; ++j2)
                    #pragma unroll
                    for (int arr = 0; arr < 2; ++arr) {
                        uint32_t addr = bbase + (uint32_t)arr * 10240u
                            + (uint32_t)(warpn * 64 + j2 * 16 + (lane & 15)) * 80u
                            + (uint32_t)(s * 32 + (lane >> 4) * 16);
                        ldm4(b[j2][arr], addr);
                    }
                #pragma unroll
                for (int i = 0; i < 2; ++i)
                    #pragma unroll
                    for (int j = 0; j < 8; ++j) {
                        int j2 = j >> 1, sub = j & 1;
                        uint32_t bh0 = b[j2][0][sub], bh1 = b[j2][0][sub + 2];
                        uint32_t bl0 = b[j2][1][sub], bl1 = b[j2][1][sub + 2];
                        mma_f16(acc[i][j], a[i][0], bh0, bh1);  // hi*hi
                        mma_f16(acc[i][j], a[i][0], bl0, bl1);  // hi*lo
                        mma_f16(acc[i][j], a[i][1], bh0, bh1);  // lo*hi
                    }
            }
            if (c + 1 < NCH) CPA_WAIT0();
            __syncthreads();
        }

        // ---- epilogue: stage + warp-parallel streaming top-32 ------------
        #pragma unroll
        for (int h = 0; h < 2; ++h) {
            if (warpn == h) {
                #pragma unroll
                for (int i = 0; i < 2; ++i)
                    #pragma unroll
                    for (int j = 0; j < 8; ++j) {
                        int row = warpm * 32 + i * 16 + (lane >> 2);
                        int col = j * 8 + 2 * (lane & 3);
                        Cs[row * CS_STR + col]           = acc[i][j][0];
                        Cs[row * CS_STR + col + 1]       = acc[i][j][1];
                        Cs[(row + 8) * CS_STR + col]     = acc[i][j][2];
                        Cs[(row + 8) * CS_STR + col + 1] = acc[i][j][3];
                    }
            }
            __syncthreads();

            #pragma unroll
            for (int rr = 0; rr < 16; ++rr) {
                int r = wid * 16 + rr;
                #pragma unroll
                for (int h2 = 0; h2 < 2; ++h2) {
                    float v  = Cs[r * CS_STR + h2 * 32 + lane];
                    int   gi = ct * 128 + h * 64 + h2 * 32 + lane;
                    float thr = tmn[r];                 // stale lower bound
                    unsigned ball = __ballot_sync(0xffffffffu, v > thr);
                    if (ball) {
                        float lastmv = thr;
                        while (ball) {
                            int src = __ffs(ball) - 1;
                            ball &= ball - 1;
                            float vv = __shfl_sync(0xffffffffu, v, src);
                            int   ii = __shfl_sync(0xffffffffu, gi, src);
                            // warp-parallel min over the row's 32 slots
                            float mv = rtv[rr]; int ml = lane;
                            #pragma unroll
                            for (int o = 16; o > 0; o >>= 1) {
                                float omv = __shfl_down_sync(0xffffffffu, mv, o);
                                int   oml = __shfl_down_sync(0xffffffffu, ml, o);
                                if (omv < mv) { mv = omv; ml = oml; }
                            }
                            mv = __shfl_sync(0xffffffffu, mv, 0);
                            ml = __shfl_sync(0xffffffffu, ml, 0);
                            if (vv > mv && lane == ml) { rtv[rr] = vv; rti[rr] = ii; }
                            lastmv = mv;
                        }
                        if (lane == 0) tmn[r] = lastmv;  // tightened bound
                    }
                }
            }
            __syncthreads();
        }
    }

    // ---- write candidate lists (one slot per lane) -----------------------
    #pragma unroll
    for (int rr = 0; rr < 16; ++rr) {
        size_t base = (size_t)(rb + wid * 16 + rr) * (NCC * KA)
                    + (size_t)cc * KA + lane;
        g_pv[base] = rtv[rr];
        g_pi[base] = rti[rr];
    }
}

// ---------------------------------------------------------------------------
// Kernel 3: per-row — merge 4x32 candidates to approx-top-64, rescore each
// with R1-style plain fp32 sequential fma chain (matches reference rounding
// behaviour empirically), select top-31 (value desc, index asc), write row.
// ---------------------------------------------------------------------------
__global__ __launch_bounds__(256)
void merge_rescore_kernel(float* __restrict__ out) {
    const int row = blockIdx.x;
    const int tid = threadIdx.x, wid = tid >> 5, lane = tid & 31;

    __shared__ __align__(16) float rowe[DD];
    __shared__ int   api[NCAND];
    __shared__ float rsv[NCAND];

    rowe[tid] = g_emb[(size_t)row * DD + tid];   // 256 threads == DD

    float* orow = out + (size_t)row * NN;

    if (wid == 0) {
        // load 128 candidates (4 per lane), approx-select top-64
        const size_t base = (size_t)row * (NCC * KA);
        float v[4]; int ci[4];
        #pragma unroll
        for (int q = 0; q < 4; ++q) {
            int j = lane + 32 * q;
            v[q]  = g_pv[base + j];
            ci[q] = g_pi[base + j];
        }
        for (int it = 0; it < NCAND; ++it) {
            float bm = -1e30f; int bq = 0;
            #pragma unroll
            for (int q = 0; q < 4; ++q) if (v[q] > bm) { bm = v[q]; bq = q; }
            float rm = bm; int rl = lane;
            #pragma unroll
            for (int o = 16; o > 0; o >>= 1) {
                float om = __shfl_down_sync(0xffffffffu, rm, o);
                int   ol = __shfl_down_sync(0xffffffffu, rl, o);
                if (om > rm) { rm = om; rl = ol; }
            }
            rl = __shfl_sync(0xffffffffu, rl, 0);
            if (lane == rl) { api[it] = ci[bq]; v[bq] = -1e30f; }
            __syncwarp();
        }
    } else {
        // zero the output row (224 threads)
        float4 z = make_float4(0.f, 0.f, 0.f, 0.f);
        for (int i = tid - 32; i < NN / 4; i += 224)
            *(float4*)(orow + i * 4) = z;
    }
    __syncthreads();

    // ---- rescore: one thread per candidate, R1-identical fp32 chain ------
    if (tid < NCAND) {
        int idx = api[tid];
        const float4* __restrict__ arow = (const float4*)rowe;
        const float4* __restrict__ brow =
            (const float4*)&g_emb[(size_t)idx * DD];
        float acc = 0.0f;
        #pragma unroll 4
        for (int d4 = 0; d4 < DD / 4; ++d4) {
            float4 a = arow[d4];
            float4 b = brow[d4];
            acc += a.x * b.x + a.y * b.y + a.z * b.z + a.w * b.w;
        }
        rsv[tid] = acc;
    }
    __syncthreads();

    // ---- final: top-31 of 64 by (value desc, index asc); write -----------
    if (wid == 0) {
        float vv[2]; int ii[2];
        vv[0] = rsv[lane];      ii[0] = api[lane];
        vv[1] = rsv[lane + 32]; ii[1] = api[lane + 32];

        for (int it = 0; it < TOPK; ++it) {
            float bv; int bi, bs;
            if (vv[0] > vv[1] || (vv[0] == vv[1] && ii[0] < ii[1])) {
                bv = vv[0]; bi = ii[0]; bs = 0;
            } else {
                bv = vv[1]; bi = ii[1]; bs = 1;
            }
            float rv = bv; int ri = bi, rl = lane;
            #pragma unroll
            for (int o = 16; o > 0; o >>= 1) {
                float ov = __shfl_down_sync(0xffffffffu, rv, o);
                int   oi = __shfl_down_sync(0xffffffffu, ri, o);
                int   ol = __shfl_down_sync(0xffffffffu, rl, o);
                if (ov > rv || (ov == rv && oi < ri)) { rv = ov; ri = oi; rl = ol; }
            }
            rl = __shfl_sync(0xffffffffu, rl, 0);
            if (lane == rl) {
                orow[bi] = fmaxf(bv, 0.0f);
                vv[bs] = -1e30f; ii[bs] = 0x7fffffff;
            }
            __syncwarp();
        }
    }
}

// ---------------------------------------------------------------------------
extern "C" void kernel_launch(void* const* d_in, const int* in_sizes, int n_in,
                              void* d_out, int out_size) {
    const float* f  = (const float*)d_in[0];
    const float* w1 = (const float*)d_in[1];
    const float* w2 = (const float*)d_in[2];
    float* out = (float*)d_out;

    emb_kernel<<<NN, DD>>>(f, w1, w2);

    cudaFuncSetAttribute(gemm_cand_kernel,
                         cudaFuncAttributeMaxDynamicSharedMemorySize, SM_END);
    gemm_cand_kernel<<<RT * NCC, 256, SM_END>>>(0);

    merge_rescore_kernel<<<NN, 256>>>(out);
}

// round 17
// speedup vs baseline: 5.0527x; 1.6455x over previous
#include <cuda_runtime.h>
#include <cuda_fp16.h>
#include <math.h>
#include <stdint.h>

// ---------------------------------------------------------------------------
// Problem constants
// ---------------------------------------------------------------------------
#define NN    10240
#define DD    256
#define TOPK  31         // final k+1
#define KA    32         // per-chunk candidate list size (register-resident)
#define NCC   4          // column chunks per row
#define CTPB  20         // col tiles (128) per chunk: 4*20*128 = 10240
#define RT    80         // row tiles (NN/128)
#define NITEMS (RT * NCC)
#define NCAND 64         // rescored candidates per row
#define NBLK  148        // persistent blocks
#define NTHR  512

// Scratch (device globals — no allocation allowed)
__device__ float  g_emb[(size_t)NN * DD];
__device__ __half g_hi[(size_t)NN * DD];
__device__ float g_pv[(size_t)NN * NCC * KA];
__device__ int   g_pi[(size_t)NN * NCC * KA];
__device__ int   g_ctr;

// ---------------------------------------------------------------------------
// Smem layout (bytes).
// A: 128 rows x 528B (512B data for K=256 fp16 + 16B pad); 132 words ≡ 4
//    mod 32 → conflict-free ldmatrix (layout proven in R12).
// B: 128 rows x 144B (128B data for K=64 chunk + 16B pad); 36 ≡ 4 mod 32.
// ---------------------------------------------------------------------------
#define SM_A    0u
#define ASTR    528u
#define SM_BB   67584u       // two bufs of 18432 (128 x 144)
#define BSTR    144u
#define BUFSZ   18432u
#define SM_CS   67584u       // C staging overlays B-buf region (128*68*4=34816)
#define CS_STR  68
#define SM_TMN  104448u      // 128 fp32 stale filter mins
#define SM_END  104960u

// ---------------------------------------------------------------------------
// PTX helpers (baseline sm_80-era features; compile for plain sm_103)
// ---------------------------------------------------------------------------
__device__ __forceinline__ uint32_t s2u(const void* p) {
    uint32_t a;
    asm("{ .reg .u64 t; cvta.to.shared.u64 t, %1; cvt.u32.u64 %0, t; }"
        : "=r"(a) : "l"(p));
    return a;
}
__device__ __forceinline__ void cpa16(uint32_t s, const void* g) {
    asm volatile(
        "{ .reg .u64 gg; cvta.to.global.u64 gg, %1; "
        "cp.async.cg.shared.global [%0], [gg], 16; }"
        :: "r"(s), "l"(g) : "memory");
}
#define CPA_COMMIT() asm volatile("cp.async.commit_group;" ::: "memory")
#define CPA_WAIT0()  asm volatile("cp.async.wait_group 0;" ::: "memory")

__device__ __forceinline__ void ldm4(uint32_t* r, uint32_t a) {
    asm volatile("ldmatrix.sync.aligned.m8n8.x4.shared.b16 {%0,%1,%2,%3}, [%4];"
                 : "=r"(r[0]), "=r"(r[1]), "=r"(r[2]), "=r"(r[3]) : "r"(a));
}
__device__ __forceinline__ void mma_f16(float* d, const uint32_t* a,
                                        uint32_t b0, uint32_t b1) {
    asm volatile(
        "mma.sync.aligned.m16n8k16.row.col.f32.f16.f16.f32 "
        "{%0,%1,%2,%3}, {%4,%5,%6,%7}, {%8,%9}, {%0,%1,%2,%3};"
        : "+f"(d[0]), "+f"(d[1]), "+f"(d[2]), "+f"(d[3])
        : "r"(a[0]), "r"(a[1]), "r"(a[2]), "r"(a[3]), "r"(b0), "r"(b1));
}

// ---------------------------------------------------------------------------
// Kernel 1: h = relu(x*w1)*w2; emb = h/max(||h||,1e-12).
// Stores fp32 emb (exact rescoring) and single fp16 (candidate MMA).
// Also resets the persistent-GEMM work-queue counter.
// ---------------------------------------------------------------------------
__global__ void emb_kernel(const float* __restrict__ f,
                           const float* __restrict__ w1,
                           const float* __restrict__ w2) {
    if (blockIdx.x == 0 && threadIdx.x == 0) g_ctr = 0;
    int row = blockIdx.x;
    int d   = threadIdx.x;            // 256 == DD
    float x = f[(size_t)row * DD + d];
    float h = fmaxf(x * w1[d], 0.0f) * w2[d];
    float s = h * h;
    __shared__ float red[8];
    #pragma unroll
    for (int o = 16; o > 0; o >>= 1) s += __shfl_xor_sync(0xffffffffu, s, o);
    if ((d & 31) == 0) red[d >> 5] = s;
    __syncthreads();
    if (d < 32) {
        float t = (d < 8) ? red[d] : 0.0f;
        #pragma unroll
        for (int o = 4; o > 0; o >>= 1) t += __shfl_xor_sync(0xffffffffu, t, o);
        if (d == 0) red[0] = t;
    }
    __syncthreads();
    float norm = fmaxf(sqrtf(red[0]), 1e-12f);
    float e = h / norm;
    size_t idx = (size_t)row * DD + d;
    g_emb[idx] = e;
    g_hi[idx]  = __float2half_rn(e);
}

// ---------------------------------------------------------------------------
// B chunk loader: B rows ct*128..+127, K cols [c*64, c*64+64)
// ---------------------------------------------------------------------------
__device__ __forceinline__ void load_B_chunk(uint32_t sb, int ct, int c,
                                             int buf, int tid) {
    uint32_t bbase = sb + SM_BB + (uint32_t)buf * BUFSZ;
    #pragma unroll
    for (int q = 0; q < 2; ++q) {
        int i = tid + q * NTHR;            // 1024 x 16B transfers
        int n = i >> 3, seg = i & 7;       // 128 rows x 8 segs (128B data)
        const void* g = &g_hi[(size_t)(ct * 128 + n) * DD + c * 64 + seg * 8];
        uint32_t s = bbase + (uint32_t)n * BSTR + (uint32_t)seg * 16u;
        cpa16(s, g);
    }
}

// ---------------------------------------------------------------------------
// Kernel 2: persistent fp16 (1-term) MMA GEMM + register-resident per-row
// top-32 candidate lists. Work item = (rt, cc): 128 rows x 2560 cols.
// 512 threads, 16 warps in 4m x 4n grid, 32x32 warp tiles.
// ---------------------------------------------------------------------------
__global__ __launch_bounds__(NTHR, 1)
void gemm_cand_kernel(int _unused) {
    extern __shared__ __align__(16) char sm[];
    uint32_t sb = s2u(sm);
    __shared__ int s_item;

    const int tid   = threadIdx.x;
    const int wid   = tid >> 5, lane = tid & 31;
    const int warpm = wid >> 2, warpn = wid & 3;

    float* tmn = (float*)(sm + SM_TMN);
    float* Cs  = (float*)(sm + SM_CS);

    for (;;) {
        if (tid == 0) s_item = atomicAdd(&g_ctr, 1);
        __syncthreads();
        const int item = s_item;
        __syncthreads();
        if (item >= NITEMS) break;

        const int rt = item >> 2;         // 0..79
        const int cc = item & 3;          // 0..3
        const int rb = rt * 128;

        // ---- load A tile (hi, full K=256), cp.async ----------------------
        #pragma unroll
        for (int q = 0; q < 8; ++q) {
            int i = tid + q * NTHR;        // 4096 x 16B = 128 rows x 32 segs
            int m = i >> 5, seg = i & 31;
            const void* g = &g_hi[(size_t)(rb + m) * DD + seg * 8];
            uint32_t s = sb + SM_A + (uint32_t)m * ASTR + (uint32_t)seg * 16u;
            cpa16(s, g);
        }
        CPA_COMMIT();

        if (tid < 128) tmn[tid] = -1e30f;

        // register candidate lists: warp owns rows wid*8..+7
        float rtv[8]; int rti[8];
        #pragma unroll
        for (int rr = 0; rr < 8; ++rr) { rtv[rr] = -1e30f; rti[rr] = 0; }

        CPA_WAIT0();
        __syncthreads();

        for (int t = 0; t < CTPB; ++t) {
            const int ct = cc * CTPB + t;

            float acc[2][4][4];
            #pragma unroll
            for (int i = 0; i < 2; ++i)
                #pragma unroll
                for (int j = 0; j < 4; ++j)
                    #pragma unroll
                    for (int q = 0; q < 4; ++q) acc[i][j][q] = 0.0f;

            load_B_chunk(sb, ct, 0, 0, tid);
            CPA_COMMIT(); CPA_WAIT0();
            __syncthreads();

            #pragma unroll
            for (int c = 0; c < 4; ++c) {           // K chunks of 64
                if (c + 1 < 4) {
                    load_B_chunk(sb, ct, c + 1, (c + 1) & 1, tid);
                    CPA_COMMIT();
                }
                uint32_t bbase = sb + SM_BB + (uint32_t)(c & 1) * BUFSZ;

                #pragma unroll
                for (int s = 0; s < 4; ++s) {       // four k16 steps
                    uint32_t a[2][4];
                    #pragma unroll
                    for (int i = 0; i < 2; ++i) {
                        uint32_t addr = sb + SM_A
                            + (uint32_t)(warpm * 32 + i * 16 + (lane & 15)) * ASTR
                            + (uint32_t)(c * 128 + s * 32 + (lane >> 4) * 16);
                        ldm4(a[i], addr);
                    }
                    uint32_t b[2][4];
                    #pragma unroll
                    for (int j2 = 0; j2 < 2; ++j2) {
                        uint32_t addr = bbase
                            + (uint32_t)(warpn * 32 + j2 * 16 + (lane & 15)) * BSTR
                            + (uint32_t)(s * 32 + (lane >> 4) * 16);
                        ldm4(b[j2], addr);
                    }
                    #pragma unroll
                    for (int i = 0; i < 2; ++i)
                        #pragma unroll
                        for (int j = 0; j < 4; ++j) {
                            int j2 = j >> 1, sub = j & 1;
                            mma_f16(acc[i][j], a[i], b[j2][sub], b[j2][sub + 2]);
                        }
                }
                if (c + 1 < 4) CPA_WAIT0();
                __syncthreads();
            }

            // ---- epilogue: stage + scan in two 64-col halves -------------
            #pragma unroll
            for (int h = 0; h < 2; ++h) {
                if ((warpn >> 1) == h) {
                    #pragma unroll
                    for (int i = 0; i < 2; ++i)
                        #pragma unroll
                        for (int j = 0; j < 4; ++j) {
                            int row = warpm * 32 + i * 16 + (lane >> 2);
                            int col = (warpn & 1) * 32 + j * 8 + 2 * (lane & 3);
                            Cs[row * CS_STR + col]           = acc[i][j][0];
                            Cs[row * CS_STR + col + 1]       = acc[i][j][1];
                            Cs[(row + 8) * CS_STR + col]     = acc[i][j][2];
                            Cs[(row + 8) * CS_STR + col + 1] = acc[i][j][3];
                        }
                }
                __syncthreads();

                #pragma unroll
                for (int rr = 0; rr < 8; ++rr) {
                    int r = wid * 8 + rr;
                    #pragma unroll
                    for (int h2 = 0; h2 < 2; ++h2) {
                        float v  = Cs[r * CS_STR + h2 * 32 + lane];
                        int   gi = ct * 128 + h * 64 + h2 * 32 + lane;
                        float thr = tmn[r];              // stale lower bound
                        unsigned ball = __ballot_sync(0xffffffffu, v > thr);
                        if (ball) {
                            float lastmv = thr;
                            while (ball) {
                                int src = __ffs(ball) - 1;
                                ball &= ball - 1;
                                float vv = __shfl_sync(0xffffffffu, v, src);
                                int   ii = __shfl_sync(0xffffffffu, gi, src);
                                float mv = rtv[rr]; int ml = lane;
                                #pragma unroll
                                for (int o = 16; o > 0; o >>= 1) {
                                    float omv = __shfl_down_sync(0xffffffffu, mv, o);
                                    int   oml = __shfl_down_sync(0xffffffffu, ml, o);
                                    if (omv < mv) { mv = omv; ml = oml; }
                                }
                                mv = __shfl_sync(0xffffffffu, mv, 0);
                                ml = __shfl_sync(0xffffffffu, ml, 0);
                                if (vv > mv && lane == ml) { rtv[rr] = vv; rti[rr] = ii; }
                                lastmv = mv;
                            }
                            if (lane == 0) tmn[r] = lastmv;
                        }
                    }
                }
                __syncthreads();
            }
        }

        // ---- write candidate lists (one slot per lane) -------------------
        #pragma unroll
        for (int rr = 0; rr < 8; ++rr) {
            size_t base = (size_t)(rb + wid * 8 + rr) * (NCC * KA)
                        + (size_t)cc * KA + lane;
            g_pv[base] = rtv[rr];
            g_pi[base] = rti[rr];
        }
        __syncthreads();
    }
}

// ---------------------------------------------------------------------------
// Kernel 3: per-row — merge 4x32 candidates to approx-top-64, rescore each
// with R1-style plain fp32 sequential chain (matches reference rounding
// behaviour empirically), select top-31 (value desc, index asc), write row.
// ---------------------------------------------------------------------------
__global__ __launch_bounds__(256)
void merge_rescore_kernel(float* __restrict__ out) {
    const int row = blockIdx.x;
    const int tid = threadIdx.x, wid = tid >> 5, lane = tid & 31;

    __shared__ __align__(16) float rowe[DD];
    __shared__ int   api[NCAND];
    __shared__ float rsv[NCAND];

    rowe[tid] = g_emb[(size_t)row * DD + tid];   // 256 threads == DD

    float* orow = out + (size_t)row * NN;

    if (wid == 0) {
        // load 128 candidates (4 per lane), approx-select top-64
        const size_t base = (size_t)row * (NCC * KA);
        float v[4]; int ci[4];
        #pragma unroll
        for (int q = 0; q < 4; ++q) {
            int j = lane + 32 * q;
            v[q]  = g_pv[base + j];
            ci[q] = g_pi[base + j];
        }
        for (int it = 0; it < NCAND; ++it) {
            float bm = -1e30f; int bq = 0;
            #pragma unroll
            for (int q = 0; q < 4; ++q) if (v[q] > bm) { bm = v[q]; bq = q; }
            float rm = bm; int rl = lane;
            #pragma unroll
            for (int o = 16; o > 0; o >>= 1) {
                float om = __shfl_down_sync(0xffffffffu, rm, o);
                int   ol = __shfl_down_sync(0xffffffffu, rl, o);
                if (om > rm) { rm = om; rl = ol; }
            }
            rl = __shfl_sync(0xffffffffu, rl, 0);
            if (lane == rl) { api[it] = ci[bq]; v[bq] = -1e30f; }
            __syncwarp();
        }
    } else {
        // zero the output row (224 threads)
        float4 z = make_float4(0.f, 0.f, 0.f, 0.f);
        for (int i = tid - 32; i < NN / 4; i += 224)
            *(float4*)(orow + i * 4) = z;
    }
    __syncthreads();

    // ---- rescore: one thread per candidate, R1-identical fp32 chain ------
    if (tid < NCAND) {
        int idx = api[tid];
        const float4* __restrict__ arow = (const float4*)rowe;
        const float4* __restrict__ brow =
            (const float4*)&g_emb[(size_t)idx * DD];
        float acc = 0.0f;
        #pragma unroll 4
        for (int d4 = 0; d4 < DD / 4; ++d4) {
            float4 a = arow[d4];
            float4 b = brow[d4];
            acc += a.x * b.x + a.y * b.y + a.z * b.z + a.w * b.w;
        }
        rsv[tid] = acc;
    }
    __syncthreads();

    // ---- final: top-31 of 64 by (value desc, index asc); write -----------
    if (wid == 0) {
        float vv[2]; int ii[2];
        vv[0] = rsv[lane];      ii[0] = api[lane];
        vv[1] = rsv[lane + 32]; ii[1] = api[lane + 32];

        for (int it = 0; it < TOPK; ++it) {
            float bv; int bi, bs;
            if (vv[0] > vv[1] || (vv[0] == vv[1] && ii[0] < ii[1])) {
                bv = vv[0]; bi = ii[0]; bs = 0;
            } else {
                bv = vv[1]; bi = ii[1]; bs = 1;
            }
            float rv = bv; int ri = bi, rl = lane;
            #pragma unroll
            for (int o = 16; o > 0; o >>= 1) {
                float ov = __shfl_down_sync(0xffffffffu, rv, o);
                int   oi = __shfl_down_sync(0xffffffffu, ri, o);
                int   ol = __shfl_down_sync(0xffffffffu, rl, o);
                if (ov > rv || (ov == rv && oi < ri)) { rv = ov; ri = oi; rl = ol; }
            }
            rl = __shfl_sync(0xffffffffu, rl, 0);
            if (lane == rl) {
                orow[bi] = fmaxf(bv, 0.0f);
                vv[bs] = -1e30f; ii[bs] = 0x7fffffff;
            }
            __syncwarp();
        }
    }
}

// ---------------------------------------------------------------------------
extern "C" void kernel_launch(void* const* d_in, const int* in_sizes, int n_in,
                              void* d_out, int out_size) {
    const float* f  = (const float*)d_in[0];
    const float* w1 = (const float*)d_in[1];
    const float* w2 = (const float*)d_in[2];
    float* out = (float*)d_out;

    emb_kernel<<<NN, DD>>>(f, w1, w2);

    cudaFuncSetAttribute(gemm_cand_kernel,
                         cudaFuncAttributeMaxDynamicSharedMemorySize, SM_END);
    gemm_cand_kernel<<<NBLK, NTHR, SM_END>>>(0);

    merge_rescore_kernel<<<NN, 256>>>(out);
}